// round 13
// baseline (speedup 1.0000x reference)
#include <cuda_runtime.h>

#define S        48
#define C        32
#define SSS      (S*S*S)          // 110592
#define SLOTS    27               // (i,j) slots per round; 3 rounds * 27 = 81
#define RANGES   12               // d split into 12 ranges of 4
#define NTHREADS 352              // 324 compute/loader threads + pad to 11 warps
#define CCH      4                // channels per chunk
#define NCHUNK   8                // 32 / 4
#define NSTAGE   3
#define CH_TOTAL (NCHUNK*3)       // 24 chunks across all 3 rounds
#define SLOT_STRIDE 80            // 80 % 32 == 16 -> LDS.128 conflict-free
#define X2STAGE  (CCH*SLOTS*SLOT_STRIDE)   // 8640 floats per stage
#define X1SZ     (C*S)            // 1536 floats
#define SOFFN    81
#define SMEM_BYTES ((X1SZ + NSTAGE*X2STAGE + SOFFN)*4)   // 110,292 bytes

typedef unsigned long long u64;

__device__ __forceinline__ void cp_async16(unsigned dst, const void* src, unsigned sz) {
    asm volatile("cp.async.cg.shared.global [%0], [%1], 16, %2;"
                 :: "r"(dst), "l"(src), "r"(sz) : "memory");
}
__device__ __forceinline__ void cp_commit() {
    asm volatile("cp.async.commit_group;" ::: "memory");
}
template<int N>
__device__ __forceinline__ void cp_wait() {
    asm volatile("cp.async.wait_group %0;" :: "n"(N) : "memory");
}

// ---- packed fp32 helpers (sm_103a dual-FMA path) ----
__device__ __forceinline__ u64 fpack(float lo, float hi) {
    u64 r; asm("mov.b64 %0, {%1, %2};" : "=l"(r) : "f"(lo), "f"(hi)); return r;
}
__device__ __forceinline__ void funpack(u64 v, float& lo, float& hi) {
    asm("mov.b64 {%0, %1}, %2;" : "=f"(lo), "=f"(hi) : "l"(v));
}
__device__ __forceinline__ u64 ffma2(u64 a, u64 b, u64 c) {
    u64 d; asm("fma.rn.f32x2 %0, %1, %2, %3;" : "=l"(d) : "l"(a), "l"(b), "l"(c)); return d;
}
__device__ __forceinline__ u64 fmul2(u64 a, u64 b) {
    u64 d; asm("mul.rn.f32x2 %0, %1, %2;" : "=l"(d) : "l"(a), "l"(b)); return d;
}
// streaming (evict-first) 16B store: output is write-once, keep x2 in L2
__device__ __forceinline__ void stcs16(float* p, u64 lo, u64 hi) {
    asm volatile("st.global.cs.v2.b64 [%0], {%1, %2};"
                 :: "l"(p), "l"(lo), "l"(hi) : "memory");
}

__global__ __launch_bounds__(NTHREADS, 2)
void corr3d_kernel(const float* __restrict__ x1,
                   const float* __restrict__ x2,
                   float* __restrict__ out)
{
    extern __shared__ float smem[];
    float* x1s = smem;                           // [C][48]
    float* x2s = smem + X1SZ;                    // [NSTAGE][CCH][SLOTS][SLOT_STRIDE]
    int*   soffs = (int*)(smem + X1SZ + NSTAGE * X2STAGE);  // [81]

    const int h   = blockIdx.x;
    const int w   = blockIdx.y;
    const int tid = threadIdx.x;

    const unsigned x2s_base = (unsigned)__cvta_generic_to_shared(x2s);

    // x1 column (32ch x 48d): 384 float4 loads over 352 threads.
    #pragma unroll 1
    for (int t = tid; t < C * 12; t += NTHREADS) {
        int c = t / 12, vq = t % 12;
        const float4* src = (const float4*)(x1 + (((size_t)c * S + h) * S + w) * S) + vq;
        ((float4*)x1s)[c * 12 + vq] = *src;
    }

    // Per-(round,slot) source offsets: off = (hh*S+ww)*S, or -1 if OOB.
    if (tid < SOFFN) {
        int oi = tid / 9, oj = tid - oi * 9;
        int hh = h + oi - 4, ww = w + oj - 4;
        soffs[tid] = (((unsigned)hh < S) && ((unsigned)ww < S)) ? (hh * S + ww) * S : -1;
    }

    // Pre-zero pad fringes (bd 0..3 and 52..55) of all stages.
    {
        float4 z = make_float4(0.f, 0.f, 0.f, 0.f);
        #pragma unroll 1
        for (int it = tid; it < NSTAGE * CCH * SLOTS * 2; it += NTHREADS) {
            int stage = it / (CCH * SLOTS * 2);
            int r     = it - stage * (CCH * SLOTS * 2);
            int row   = r >> 1;
            int p     = r & 1;
            ((float4*)x2s)[(stage * X2STAGE + row * SLOT_STRIDE) / 4 + (p ? 13 : 0)] = z;
        }
    }

    const bool loader = (tid < SLOTS * RANGES);   // 324
    const int  slot   = tid / RANGES;
    const int  vr     = tid % RANGES;
    const int  d0     = vr * 4;
    const bool active = loader;
    const u64  inv2   = fpack(1.0f / (float)C, 1.0f / (float)C);

    // Hoisted per-thread loader constants: 4 items per chunk (t = j*27 + slot).
    const float* pj[4];
    unsigned     dstj[4];
    int          slj[4];
    #pragma unroll
    for (int j = 0; j < 4; ++j) {
        int t  = j * SLOTS + slot;     // 0..107 (meaningful only when loader)
        int c  = t & 3;
        int sl = t >> 2;
        slj[j]  = sl;
        pj[j]   = x2 + (size_t)c * SSS + d0;
        dstj[j] = x2s_base + (unsigned)((c * SLOTS + sl) * SLOT_STRIDE + d0 + 4) * 4u;
    }

    __syncthreads();   // smem init visible before first issues

    // issue chunk ch into stage at byte-offset isb
    auto issue = [&](int ch, unsigned isb) {
        if (loader) {
            int r2  = ch >> 3;
            int cc2 = ch & 7;
            size_t cshift = (size_t)(cc2 * CCH) * SSS;
            const int* so = soffs + r2 * SLOTS;
            #pragma unroll
            for (int j = 0; j < 4; ++j) {
                int off = so[slj[j]];
                bool valid = (off >= 0);
                const float* src = pj[j] + cshift + (valid ? off : 0);
                cp_async16(dstj[j] + isb, src, valid ? 16u : 0u);
            }
        }
        cp_commit();
    };

    issue(0, 0u);
    issue(1, (unsigned)(X2STAGE * 4));

    u64 acc2[18];
    #pragma unroll
    for (int i = 0; i < 18; ++i) acc2[i] = 0ull;

    int      compF = 0;                               // float offset of compute stage
    unsigned issB  = (unsigned)(2 * X2STAGE * 4);     // byte offset of issue stage

    #pragma unroll 1
    for (int g = 0; g < CH_TOTAL; ++g) {
        if (g < CH_TOTAL - 1) cp_wait<1>(); else cp_wait<0>();
        __syncthreads();

        if (g + 2 < CH_TOTAL) issue(g + 2, issB);
        issB += (unsigned)(X2STAGE * 4);
        if (issB == (unsigned)(NSTAGE * X2STAGE * 4)) issB = 0;

        if (active) {
            const float* xb = x2s + compF;
            const int cg0 = (g & 7) * CCH;
            #pragma unroll
            for (int c = 0; c < CCH; ++c) {
                const ulonglong2 a2 = *(const ulonglong2*)(x1s + (cg0 + c) * S + d0);
                const u64 av01 = a2.x, av23 = a2.y;

                const float* wr = xb + (c * SLOTS + slot) * SLOT_STRIDE + d0;
                const ulonglong2 w0 = *(const ulonglong2*)(wr);      // (0,1)(2,3)
                const ulonglong2 w1 = *(const ulonglong2*)(wr + 4);  // (4,5)(6,7)
                const ulonglong2 w2 = *(const ulonglong2*)(wr + 8);  // (8,9)(10,11)
                u64 ep[6] = {w0.x, w0.y, w1.x, w1.y, w2.x, w2.y};

                u64 op[5];
                #pragma unroll
                for (int m = 0; m < 5; ++m) {
                    float l0, h0, l1, h1;
                    funpack(ep[m], l0, h0);
                    funpack(ep[m + 1], l1, h1);
                    op[m] = fpack(h0, l1);
                }

                #pragma unroll
                for (int k = 0; k < 9; ++k) {
                    u64 b01 = (k & 1) ? op[(k - 1) >> 1] : ep[k >> 1];
                    u64 b23 = (k & 1) ? op[(k + 1) >> 1] : ep[(k >> 1) + 1];
                    acc2[2 * k]     = ffma2(av01, b01, acc2[2 * k]);
                    acc2[2 * k + 1] = ffma2(av23, b23, acc2[2 * k + 1]);
                }
            }
        }
        compF += X2STAGE;
        if (compF == NSTAGE * X2STAGE) compF = 0;

        if ((g & 7) == 7) {
            if (active) {
                const int ij = (g >> 3) * SLOTS + slot;   // out channel = ij*9 + k
                float* obase = out + (size_t)ij * 9 * SSS + ((size_t)h * S + w) * S + d0;
                #pragma unroll
                for (int k = 0; k < 9; ++k) {
                    stcs16(obase + (size_t)k * SSS,
                           fmul2(acc2[2 * k], inv2),
                           fmul2(acc2[2 * k + 1], inv2));
                }
            }
            #pragma unroll
            for (int i = 0; i < 18; ++i) acc2[i] = 0ull;
        }
    }
}

extern "C" void kernel_launch(void* const* d_in, const int* in_sizes, int n_in,
                              void* d_out, int out_size)
{
    const float* x1 = (const float*)d_in[0];
    const float* x2 = (const float*)d_in[1];
    float* out = (float*)d_out;

    cudaFuncSetAttribute(corr3d_kernel,
                         cudaFuncAttributeMaxDynamicSharedMemorySize, SMEM_BYTES);
    dim3 grid(S, S);
    corr3d_kernel<<<grid, NTHREADS, SMEM_BYTES>>>(x1, x2, out);
}